// round 14
// baseline (speedup 1.0000x reference)
#include <cuda_runtime.h>
#include <cstdint>

#define MAXPERK 200000

// ---------------- static device scratch (no allocations allowed) ----------------
__device__ float d_tmp0 [(size_t)200000 * 32];   // raw conv outputs (pre-BN)
__device__ float d_tmp1 [(size_t)200000 * 64];
__device__ float d_tmp2 [(size_t)70000  * 128];
__device__ float d_tmp2t[(size_t)200000 * 64];
__device__ float d_tmp1t[(size_t)200000 * 64];
__device__ int2  d_pairs6[6][(size_t)27 * MAXPERK];  // per-layer per-k (j, m) lists
__device__ int   d_cur6[6][32];
__device__ float d_stats6[6][256];               // [0..C) sum, [128..128+C) sumsq
__device__ float d_ss6[6][256];                  // [0..C) scale, [128..128+C) shift
__device__ int   d_cnt6[6];

// ---------------- tiny utility kernels ----------------
__global__ void prep_kernel() {
    int t = threadIdx.x;
    for (int i = t; i < 6 * 32; i += 256)  ((int*)d_cur6)[i] = 0;
    for (int i = t; i < 6 * 256; i += 256) ((float*)d_stats6)[i] = 0.f;
    if (t < 6) d_cnt6[t] = 0;
}

__global__ void zero_ptr_kernel(float* __restrict__ p, long n) {
    long n4 = n >> 2;
    float4* p4 = (float4*)p;
    for (long i = (long)blockIdx.x * blockDim.x + threadIdx.x; i < n4;
         i += (long)gridDim.x * blockDim.x)
        p4[i] = make_float4(0.f, 0.f, 0.f, 0.f);
    if (blockIdx.x == 0 && threadIdx.x < (n & 3)) p[n4 * 4 + threadIdx.x] = 0.f;
}

// compact valid (k, j, m) into per-k lists — warp-aggregated atomics
__device__ __forceinline__ void fill_body(int i, const int* __restrict__ map, int Nout,
                                          int2* __restrict__ pairs, int* __restrict__ cur) {
    int total = 27 * Nout;
    bool valid = false;
    int m = 0, k = 0, j = 0;
    if (i < total) {
        m = map[i];
        if (m >= 0) { valid = true; k = i / Nout; j = i - k * Nout; }
    }
    unsigned vm = __ballot_sync(0xffffffffu, valid);
    if (valid) {
        unsigned same = __match_any_sync(vm, k);   // valid lanes with equal k
        int lane = threadIdx.x & 31;
        int leader = __ffs(same) - 1;
        int rank = __popc(same & ((1u << lane) - 1));
        int base = 0;
        if (lane == leader) base = atomicAdd(&cur[k], __popc(same));
        base = __shfl_sync(same, base, leader);
        pairs[(size_t)k * MAXPERK + base + rank] = make_int2(j, m);
    }
}

__global__ void fill_kernel(const int* __restrict__ map, int Nout,
                            int2* __restrict__ pairs, int* __restrict__ cur) {
    fill_body(blockIdx.x * blockDim.x + threadIdx.x, map, Nout, pairs, cur);
}

// ---------------- vector reds + packed fp32 fma ----------------
__device__ __forceinline__ void red_add_v4(float* p, float a, float b, float c, float d) {
#if defined(__CUDA_ARCH__) && __CUDA_ARCH__ >= 900
    asm volatile("red.global.add.v4.f32 [%0], {%1, %2, %3, %4};"
                 :: "l"(p), "f"(a), "f"(b), "f"(c), "f"(d) : "memory");
#else
    atomicAdd(p + 0, a); atomicAdd(p + 1, b); atomicAdd(p + 2, c); atomicAdd(p + 3, d);
#endif
}
__device__ __forceinline__ void red_add_v2(float* p, float a, float b) {
#if defined(__CUDA_ARCH__) && __CUDA_ARCH__ >= 900
    asm volatile("red.global.add.v2.f32 [%0], {%1, %2};"
                 :: "l"(p), "f"(a), "f"(b) : "memory");
#else
    atomicAdd(p + 0, a); atomicAdd(p + 1, b);
#endif
}

// packed 2-wide fp32 fma (sm_100+): d = a*b + c elementwise on f32x2
__device__ __forceinline__ unsigned long long ffma2(unsigned long long a,
                                                    unsigned long long b,
                                                    unsigned long long c) {
    unsigned long long d;
    asm("fma.rn.f32x2 %0, %1, %2, %3;" : "=l"(d) : "l"(a), "l"(b), "l"(c));
    return d;
}
__device__ __forceinline__ float hadd2(unsigned long long v) {
    union { unsigned long long u; float2 f; } x; x.u = v;
    return x.f.x + x.f.y;
}

// ---------------- main sparse-conv (BN+ReLU-fused gather - GEMM - scatter-add) --
// Tile: 128 compacted rows x COLS cols. W[k] stored in smem K-pair-interleaved
// (Wp[ci/2][c][2]) so the fma.rn.f32x2 mainloop packs the K dimension:
// acc2[(i,c)] holds (even-ci partial, odd-ci partial); horizontal add at end.
template <int CIN, int KC, int COLS, bool BN, int MAXB>
__global__ void __launch_bounds__(16 * (COLS / 4), MAXB)
conv_scatter(const float* __restrict__ xA, const float* __restrict__ xB, int wA,
             const float* __restrict__ ssA, const float* __restrict__ ssB,
             const float* __restrict__ W, float* __restrict__ out,
             int COUT, int nCC,
             const int2* __restrict__ pairs, const int* __restrict__ cur) {
    constexpr int T   = 16 * (COLS / 4);   // threads
    constexpr int XST = KC + 4;            // xs row stride (16B-aligned rows)
    constexpr int NCH = CIN / KC;          // K chunks
    constexpr int TPR = T / 128;           // threads per row in gather
    constexpr int L   = KC / TPR;          // cols per gather thread per chunk
    constexpr int F4  = L / 4;

    extern __shared__ float sm[];
    float* xs = sm;                 // 128 * XST
    float* Ws = sm + 128 * XST;     // CIN * COLS (pair-interleaved)
    __shared__ float sss[CIN];
    __shared__ float sst[CIN];
    __shared__ int sj[128];
    __shared__ int scnt[27];
    __shared__ int sbase[28];

    const int tid = threadIdx.x;
    if (BN) {
        for (int c = tid; c < CIN; c += T) {
            const float* tab = (c < wA) ? ssA : ssB;
            int cc = (c < wA) ? c : c - wA;
            sss[c] = tab[cc];
            sst[c] = tab[128 + cc];
        }
    }
    if (tid < 27) scnt[tid] = cur[tid];
    __syncthreads();
    if (tid == 0) {
        int s = 0;
        for (int k = 0; k < 27; k++) { sbase[k] = s; s += (scnt[k] + 127) >> 7; }
        sbase[27] = s;
    }
    __syncthreads();
    const int nTiles = sbase[27];
    const long totalT = (long)nTiles * nCC;
    const int tx = tid % (COLS / 4);
    const int ty = tid / (COLS / 4);
    const int gr = tid / TPR;       // gather row
    const int gpart = tid - gr * TPR;

    const long tBeg = (long)blockIdx.x * totalT / gridDim.x;
    const long tEnd = ((long)blockIdx.x + 1) * totalT / gridDim.x;

    int kPrev = -1, ccPrev = -1;

    for (long t = tBeg; t < tEnd; t++) {
        const int cc = (int)(t / nTiles);       // cc outer -> same-k runs adjacent
        const int tileId = (int)(t - (long)cc * nTiles);
        int k = 0;
        while (sbase[k + 1] <= tileId) k++;
        const int rowBase = (tileId - sbase[k]) * 128;
        const int valid = min(scnt[k] - rowBase, 128);
        const int2* pk = &pairs[(size_t)k * MAXPERK + rowBase];
        const int colBase = cc * COLS;

        __syncthreads();  // previous tile's smem reads complete

        // load W[k] column chunk into smem, K-pair-interleaved (skip if unchanged)
        if (k != kPrev || cc != ccPrev) {
            kPrev = k; ccPrev = cc;
            const float* Wk = W + ((size_t)k * CIN) * COUT + colBase;
            #pragma unroll
            for (int idx = tid; idx < CIN * (COLS / 4); idx += T) {
                int ci = idx / (COLS / 4);
                int c4 = (idx - ci * (COLS / 4)) * 4;
                float4 w = *(const float4*)&Wk[(size_t)ci * COUT + c4];
                float* dst = &Ws[(ci >> 1) * (2 * COLS) + (ci & 1)];
                dst[(c4 + 0) * 2] = w.x;
                dst[(c4 + 1) * 2] = w.y;
                dst[(c4 + 2) * 2] = w.z;
                dst[(c4 + 3) * 2] = w.w;
            }
        }

        // per-tile row pair (held in regs across chunks)
        int2 prw = (gr < valid) ? pk[gr] : make_int2(-1, -1);
        if (gpart == 0) sj[gr] = prw.x;

        unsigned long long acc2[8][4];
        #pragma unroll
        for (int i = 0; i < 8; i++)
            acc2[i][0] = acc2[i][1] = acc2[i][2] = acc2[i][3] = 0ull;

        #pragma unroll
        for (int kc = 0; kc < NCH; kc++) {
            if (kc > 0) __syncthreads();   // prev chunk's xs reads complete

            // gather chunk kc, BN+ReLU applied on the fly
            {
                const int c0 = kc * KC + gpart * L;   // global column
                float4* dst = (float4*)&xs[gr * XST + gpart * L];
                if (prw.x >= 0) {
                    const float4* src = (c0 < wA)
                        ? (const float4*)(xA + (size_t)prw.y * wA + c0)
                        : (const float4*)(xB + (size_t)prw.y * (CIN - wA) + (c0 - wA));
                    #pragma unroll
                    for (int v = 0; v < F4; v++) {
                        float4 q = src[v];
                        if (BN) {
                            const int c = c0 + 4 * v;
                            q.x = fmaxf(fmaf(q.x, sss[c + 0], sst[c + 0]), 0.f);
                            q.y = fmaxf(fmaf(q.y, sss[c + 1], sst[c + 1]), 0.f);
                            q.z = fmaxf(fmaf(q.z, sss[c + 2], sst[c + 2]), 0.f);
                            q.w = fmaxf(fmaf(q.w, sss[c + 3], sst[c + 3]), 0.f);
                        }
                        dst[v] = q;
                    }
                } else {
                    #pragma unroll
                    for (int v = 0; v < F4; v++)
                        dst[v] = make_float4(0.f, 0.f, 0.f, 0.f);
                }
            }
            __syncthreads();

            // packed-K FFMA2 over this chunk: per ci-pair, 2 LDS.128 for w pairs
            // + 8 LDS.64 for a pairs + 32 FFMA2.
            #pragma unroll 2
            for (int ci2 = 0; ci2 < KC / 2; ci2++) {
                const float* wrow = &Ws[(kc * (KC / 2) + ci2) * (2 * COLS) + tx * 8];
                const ulonglong2 wa = *(const ulonglong2*)(wrow);      // cols 0,1
                const ulonglong2 wb = *(const ulonglong2*)(wrow + 4);  // cols 2,3
                #pragma unroll
                for (int i = 0; i < 8; i++) {
                    const unsigned long long a2 =
                        *(const unsigned long long*)&xs[(ty * 8 + i) * XST + ci2 * 2];
                    acc2[i][0] = ffma2(a2, wa.x, acc2[i][0]);
                    acc2[i][1] = ffma2(a2, wa.y, acc2[i][1]);
                    acc2[i][2] = ffma2(a2, wb.x, acc2[i][2]);
                    acc2[i][3] = ffma2(a2, wb.y, acc2[i][3]);
                }
            }
        }

        // horizontal add + scatter (cross-k collisions need atomics) — 128-bit reds
        #pragma unroll
        for (int i = 0; i < 8; i++) {
            const int r = ty * 8 + i;
            if (r < valid) {
                float* op = out + (size_t)sj[r] * COUT + colBase + tx * 4;
                red_add_v4(op, hadd2(acc2[i][0]), hadd2(acc2[i][1]),
                               hadd2(acc2[i][2]), hadd2(acc2[i][3]));
            }
        }
    }
}

// ---------------- fused: BN stats+finalize (512 blocks) | zero next buffer
// (256 blocks) | fill next map (rest). Roles run concurrently in one launch.
__global__ void statsfused_kernel(const float* __restrict__ t, int n, int C,
                                  const float* __restrict__ g, const float* __restrict__ b,
                                  float* __restrict__ stats, float* __restrict__ ss,
                                  int* __restrict__ cnt,
                                  float* __restrict__ zp, long zn,
                                  const int* __restrict__ map, int Nout,
                                  int2* __restrict__ pairs, int* __restrict__ cur) {
    __shared__ float4 r1[256], r2[256];
    __shared__ int last;
    const int tid = threadIdx.x;
    const int bid = blockIdx.x;

    if (bid < 512) {
        // ---- stats role (vectorized float4) ----
        const int c4n = C / 4;          // 8 / 16 / 32
        const int c4 = tid % c4n;
        const int gi = tid / c4n;
        const int G = 256 / c4n;
        const float4* t4 = (const float4*)t;
        float4 a = make_float4(0.f, 0.f, 0.f, 0.f);
        float4 q = make_float4(0.f, 0.f, 0.f, 0.f);
        for (long row = (long)bid * G + gi; row < n; row += 512L * G) {
            float4 v = t4[row * c4n + c4];
            a.x += v.x; a.y += v.y; a.z += v.z; a.w += v.w;
            q.x += v.x * v.x; q.y += v.y * v.y; q.z += v.z * v.z; q.w += v.w * v.w;
        }
        r1[tid] = a; r2[tid] = q;
        __syncthreads();
        for (int off = 128; off >= c4n; off >>= 1) {
            if (tid < off) {
                float4 x1 = r1[tid + off], x2 = r2[tid + off];
                float4 y1 = r1[tid], y2 = r2[tid];
                y1.x += x1.x; y1.y += x1.y; y1.z += x1.z; y1.w += x1.w;
                y2.x += x2.x; y2.y += x2.y; y2.z += x2.z; y2.w += x2.w;
                r1[tid] = y1; r2[tid] = y2;
            }
            __syncthreads();
        }
        if (tid < c4n) {
            float4 a4 = r1[tid], q4 = r2[tid];
            atomicAdd(&stats[4 * tid + 0], a4.x);
            atomicAdd(&stats[4 * tid + 1], a4.y);
            atomicAdd(&stats[4 * tid + 2], a4.z);
            atomicAdd(&stats[4 * tid + 3], a4.w);
            atomicAdd(&stats[128 + 4 * tid + 0], q4.x);
            atomicAdd(&stats[128 + 4 * tid + 1], q4.y);
            atomicAdd(&stats[128 + 4 * tid + 2], q4.z);
            atomicAdd(&stats[128 + 4 * tid + 3], q4.w);
        }
        __threadfence();
        if (tid == 0) last = (atomicAdd(cnt, 1) == 511);
        __syncthreads();
        if (last && tid < C) {
            volatile float* vs = stats;
            float inv = 1.f / (float)n;
            float mu = vs[tid] * inv;
            float var = vs[128 + tid] * inv - mu * mu;
            float s = g[tid] * rsqrtf(var + 1e-5f);
            ss[tid] = s;
            ss[128 + tid] = b[tid] - mu * s;
        }
    } else if (bid < 768) {
        // ---- zero role ----
        const int bz = bid - 512;
        long n4 = zn >> 2;
        float4* p4 = (float4*)zp;
        for (long i = (long)bz * 256 + tid; i < n4; i += 256L * 256)
            p4[i] = make_float4(0.f, 0.f, 0.f, 0.f);
        if (bz == 0 && tid < (zn & 3)) zp[n4 * 4 + tid] = 0.f;
    } else {
        // ---- fill role ----
        fill_body((bid - 768) * 256 + tid, map, Nout, pairs, cur);
    }
}

// ---------------- final 96 -> 2 conv (thread per compacted pair, BN in gather) --
__global__ void conv_final_kernel(const float* __restrict__ xA,   // tmp1t [*,64]
                                  const float* __restrict__ xB,   // tmp0  [*,32]
                                  const float* __restrict__ ssA,
                                  const float* __restrict__ ssB,
                                  const float* __restrict__ W, float* __restrict__ out,
                                  const int2* __restrict__ pairs,
                                  const int* __restrict__ cur) {
    __shared__ float Ws[27 * 96 * 2];
    __shared__ float sss[96], sst[96];
    __shared__ int scnt[27];
    __shared__ int sbase[28];
    int tid = threadIdx.x;
    for (int i = tid; i < 27 * 192; i += 256) Ws[i] = W[i];
    for (int c = tid; c < 96; c += 256) {
        const float* tab = (c < 64) ? ssA : ssB;
        int cc = (c < 64) ? c : c - 64;
        sss[c] = tab[cc];
        sst[c] = tab[128 + cc];
    }
    if (tid < 27) scnt[tid] = cur[tid];
    __syncthreads();
    if (tid == 0) {
        int s = 0;
        for (int k = 0; k < 27; k++) { sbase[k] = s; s += (scnt[k] + 255) >> 8; }
        sbase[27] = s;
    }
    __syncthreads();
    int total = sbase[27];
    for (int t = blockIdx.x; t < total; t += gridDim.x) {
        int k = 0;
        while (sbase[k + 1] <= t) k++;
        int pi = (t - sbase[k]) * 256 + tid;
        if (pi < scnt[k]) {
            int2 p = pairs[(size_t)k * MAXPERK + pi];
            const float* wk = &Ws[k * 192];
            float a0 = 0.f, a1 = 0.f;
            const float4* rA = (const float4*)(xA + (size_t)p.y * 64);
            #pragma unroll
            for (int v = 0; v < 16; v++) {
                float4 q = rA[v];
                int c = 4 * v;
                q.x = fmaxf(fmaf(q.x, sss[c + 0], sst[c + 0]), 0.f);
                q.y = fmaxf(fmaf(q.y, sss[c + 1], sst[c + 1]), 0.f);
                q.z = fmaxf(fmaf(q.z, sss[c + 2], sst[c + 2]), 0.f);
                q.w = fmaxf(fmaf(q.w, sss[c + 3], sst[c + 3]), 0.f);
                a0 += q.x * wk[(c + 0) * 2 + 0]; a1 += q.x * wk[(c + 0) * 2 + 1];
                a0 += q.y * wk[(c + 1) * 2 + 0]; a1 += q.y * wk[(c + 1) * 2 + 1];
                a0 += q.z * wk[(c + 2) * 2 + 0]; a1 += q.z * wk[(c + 2) * 2 + 1];
                a0 += q.w * wk[(c + 3) * 2 + 0]; a1 += q.w * wk[(c + 3) * 2 + 1];
            }
            const float4* rB = (const float4*)(xB + (size_t)p.y * 32);
            #pragma unroll
            for (int v = 0; v < 8; v++) {
                float4 q = rB[v];
                int c = 64 + 4 * v;
                q.x = fmaxf(fmaf(q.x, sss[c + 0], sst[c + 0]), 0.f);
                q.y = fmaxf(fmaf(q.y, sss[c + 1], sst[c + 1]), 0.f);
                q.z = fmaxf(fmaf(q.z, sss[c + 2], sst[c + 2]), 0.f);
                q.w = fmaxf(fmaf(q.w, sss[c + 3], sst[c + 3]), 0.f);
                a0 += q.x * wk[(c + 0) * 2 + 0]; a1 += q.x * wk[(c + 0) * 2 + 1];
                a0 += q.y * wk[(c + 1) * 2 + 0]; a1 += q.y * wk[(c + 1) * 2 + 1];
                a0 += q.z * wk[(c + 2) * 2 + 0]; a1 += q.z * wk[(c + 2) * 2 + 1];
                a0 += q.w * wk[(c + 3) * 2 + 0]; a1 += q.w * wk[(c + 3) * 2 + 1];
            }
            red_add_v2(&out[(size_t)p.x * 2], a0, a1);
        }
    }
}

// ---------------- host orchestration ----------------
extern "C" void kernel_launch(void* const* d_in, const int* in_sizes, int n_in,
                              void* d_out, int out_size) {
    if (n_in < 23) return;
    const float* feats = (const float*)d_in[0];
    const float* W0  = (const float*)d_in[1];
    const float* g0  = (const float*)d_in[2];
    const float* b0  = (const float*)d_in[3];
    const float* W1  = (const float*)d_in[4];
    const float* g1  = (const float*)d_in[5];
    const float* b1  = (const float*)d_in[6];
    const float* W2  = (const float*)d_in[7];
    const float* g2  = (const float*)d_in[8];
    const float* b2  = (const float*)d_in[9];
    const float* W2t = (const float*)d_in[10];
    const float* g2t = (const float*)d_in[11];
    const float* b2t = (const float*)d_in[12];
    const float* W1t = (const float*)d_in[13];
    const float* g1t = (const float*)d_in[14];
    const float* b1t = (const float*)d_in[15];
    const float* W0t = (const float*)d_in[16];
    const int* map0  = (const int*)d_in[17];
    const int* map1  = (const int*)d_in[18];
    const int* map2  = (const int*)d_in[19];
    const int* map2t = (const int*)d_in[20];
    const int* map1t = (const int*)d_in[21];
    const int* map0t = (const int*)d_in[22];

    const int N0 = in_sizes[0] / 16;
    const int N1 = in_sizes[18] / 27;
    const int N2 = in_sizes[19] / 27;

    float *t0, *t1, *t2, *t2t, *t1t;
    int2 *pr; int *cu; float *st, *ss; int *cn;
    cudaGetSymbolAddress((void**)&t0,  d_tmp0);
    cudaGetSymbolAddress((void**)&t1,  d_tmp1);
    cudaGetSymbolAddress((void**)&t2,  d_tmp2);
    cudaGetSymbolAddress((void**)&t2t, d_tmp2t);
    cudaGetSymbolAddress((void**)&t1t, d_tmp1t);
    cudaGetSymbolAddress((void**)&pr,  d_pairs6);
    cudaGetSymbolAddress((void**)&cu,  d_cur6);
    cudaGetSymbolAddress((void**)&st,  d_stats6);
    cudaGetSymbolAddress((void**)&ss,  d_ss6);
    cudaGetSymbolAddress((void**)&cn,  d_cnt6);
    const size_t PK = (size_t)27 * MAXPERK;
    int2* P[6]; int* C6[6]; float* ST[6]; float* SS[6];
    for (int l = 0; l < 6; l++) {
        P[l] = pr + l * PK; C6[l] = cu + l * 32;
        ST[l] = st + l * 256; SS[l] = ss + l * 256;
    }

    // smem: 128*(KC+4)*4 (xs) + CIN*COLS*4 (pair-interleaved Ws)
    const int sm16  = (128 * 20 + 16  * 32) * 4;   // 12288
    const int sm32  = (128 * 36 + 32  * 64) * 4;   // 26624
    const int sm64  = (128 * 68 + 64  * 64) * 4;   // 51200
    const int sm128 = (128 * 68 + 128 * 64) * 4;   // 67584
    cudaFuncSetAttribute(conv_scatter<64, 64, 64, true, 2>,
                         cudaFuncAttributeMaxDynamicSharedMemorySize, sm64);
    cudaFuncSetAttribute(conv_scatter<128, 64, 64, true, 2>,
                         cudaFuncAttributeMaxDynamicSharedMemorySize, sm128);

    const int GC = 296;   // 148 SMs x 2 resident blocks (reg-heavy packed kernels)

    auto cdiv = [](long a, long b) { return (int)((a + b - 1) / b); };
    const int FB0 = cdiv(27L * N0, 256);
    const int FB1 = cdiv(27L * N1, 256);
    const int FB2 = cdiv(27L * N2, 256);

    // global init
    prep_kernel<<<1, 256>>>();
    zero_ptr_kernel<<<512, 256>>>(t0, (long)N0 * 32);

    // ---- Layer 0: feats[N0,16] -> tmp0 (raw), BN fused downstream
    fill_kernel<<<FB0, 256>>>(map0, N0, P[0], C6[0]);
    conv_scatter<16, 16, 32, false, 4><<<592, 128, sm16>>>(
        feats, (const float*)nullptr, 16, nullptr, nullptr, W0, t0, 32, 1, P[0], C6[0]);
    // stats0 | zero t1 | fill map1
    statsfused_kernel<<<768 + FB1, 256>>>(t0, N0, 32, g0, b0, ST[0], SS[0], &cn[0],
                                          t1, (long)N1 * 64, map1, N1, P[1], C6[1]);

    // ---- Layer 1: bn(tmp0) -> tmp1
    conv_scatter<32, 32, 64, true, 2><<<GC, 256, sm32>>>(
        t0, (const float*)nullptr, 32, SS[0], nullptr, W1, t1, 64, 1, P[1], C6[1]);
    statsfused_kernel<<<768 + FB2, 256>>>(t1, N1, 64, g1, b1, ST[1], SS[1], &cn[1],
                                          t2, (long)N2 * 128, map2, N2, P[2], C6[2]);

    // ---- Layer 2: bn(tmp1) -> tmp2
    conv_scatter<64, 64, 64, true, 2><<<GC, 256, sm64>>>(
        t1, (const float*)nullptr, 64, SS[1], nullptr, W2, t2, 128, 2, P[2], C6[2]);
    statsfused_kernel<<<768 + FB1, 256>>>(t2, N2, 128, g2, b2, ST[2], SS[2], &cn[2],
                                          t2t, (long)N1 * 64, map2t, N1, P[3], C6[3]);

    // ---- Layer 2t: bn(tmp2) -> tmp2t
    conv_scatter<128, 64, 64, true, 2><<<GC, 256, sm128>>>(
        t2, (const float*)nullptr, 128, SS[2], nullptr, W2t, t2t, 64, 1, P[3], C6[3]);
    statsfused_kernel<<<768 + FB0, 256>>>(t2t, N1, 64, g2t, b2t, ST[3], SS[3], &cn[3],
                                          t1t, (long)N0 * 64, map1t, N0, P[4], C6[4]);

    // ---- Layer 1t: [bn(tmp2t) | bn(tmp1)] (virtual concat, CIN=128) -> tmp1t
    conv_scatter<128, 64, 64, true, 2><<<GC, 256, sm128>>>(
        t2t, t1, 64, SS[3], SS[1], W1t, t1t, 64, 1, P[4], C6[4]);
    statsfused_kernel<<<768 + FB0, 256>>>(t1t, N0, 64, g1t, b1t, ST[4], SS[4], &cn[4],
                                          (float*)d_out, (long)out_size,
                                          map0t, N0, P[5], C6[5]);

    // ---- Layer 0t: [bn(tmp1t) | bn(tmp0)] (virtual concat, CIN=96) -> out[N0,2]
    conv_final_kernel<<<2048, 256>>>(t1t, t0, SS[4], SS[0], W0t,
                                     (float*)d_out, P[5], C6[5]);
}

// round 17
// speedup vs baseline: 1.0665x; 1.0665x over previous
#include <cuda_runtime.h>
#include <cstdint>

#define MAXPERK 200000

// ---------------- static device scratch (no allocations allowed) ----------------
__device__ float d_tmp0 [(size_t)200000 * 32];   // raw conv outputs (pre-BN)
__device__ float d_tmp1 [(size_t)200000 * 64];
__device__ float d_tmp2 [(size_t)70000  * 128];
__device__ float d_tmp2t[(size_t)200000 * 64];
__device__ float d_tmp1t[(size_t)200000 * 64];
__device__ int2  d_pairs2[2][(size_t)27 * MAXPERK];  // ping-pong per-k (j, m) lists
__device__ int   d_cur6[6][32];
__device__ float d_stats6[6][256];               // [0..C) sum, [128..128+C) sumsq
__device__ float d_ss6[6][256];                  // [0..C) scale, [128..128+C) shift
__device__ int   d_cnt6[6];

// ---------------- tiny utility kernels ----------------
__global__ void prep_kernel() {
    int t = threadIdx.x;
    for (int i = t; i < 6 * 32; i += 256)  ((int*)d_cur6)[i] = 0;
    for (int i = t; i < 6 * 256; i += 256) ((float*)d_stats6)[i] = 0.f;
    if (t < 6) d_cnt6[t] = 0;
}

__global__ void zero_ptr_kernel(float* __restrict__ p, long n) {
    long n4 = n >> 2;
    float4* p4 = (float4*)p;
    for (long i = (long)blockIdx.x * blockDim.x + threadIdx.x; i < n4;
         i += (long)gridDim.x * blockDim.x)
        p4[i] = make_float4(0.f, 0.f, 0.f, 0.f);
    if (blockIdx.x == 0 && threadIdx.x < (n & 3)) p[n4 * 4 + threadIdx.x] = 0.f;
}

// compact valid (k, j, m) into per-k lists — warp-aggregated atomics
__device__ __forceinline__ void fill_body(int i, const int* __restrict__ map, int Nout,
                                          int2* __restrict__ pairs, int* __restrict__ cur) {
    int total = 27 * Nout;
    bool valid = false;
    int m = 0, k = 0, j = 0;
    if (i < total) {
        m = map[i];
        if (m >= 0) { valid = true; k = i / Nout; j = i - k * Nout; }
    }
    unsigned vm = __ballot_sync(0xffffffffu, valid);
    if (valid) {
        unsigned same = __match_any_sync(vm, k);   // valid lanes with equal k
        int lane = threadIdx.x & 31;
        int leader = __ffs(same) - 1;
        int rank = __popc(same & ((1u << lane) - 1));
        int base = 0;
        if (lane == leader) base = atomicAdd(&cur[k], __popc(same));
        base = __shfl_sync(same, base, leader);
        pairs[(size_t)k * MAXPERK + base + rank] = make_int2(j, m);
    }
}

__global__ void fill_kernel(const int* __restrict__ map, int Nout,
                            int2* __restrict__ pairs, int* __restrict__ cur) {
    fill_body(blockIdx.x * blockDim.x + threadIdx.x, map, Nout, pairs, cur);
}

// ---------------- vector reds ----------------
__device__ __forceinline__ void red_add_v4(float* p, float a, float b, float c, float d) {
#if defined(__CUDA_ARCH__) && __CUDA_ARCH__ >= 900
    asm volatile("red.global.add.v4.f32 [%0], {%1, %2, %3, %4};"
                 :: "l"(p), "f"(a), "f"(b), "f"(c), "f"(d) : "memory");
#else
    atomicAdd(p + 0, a); atomicAdd(p + 1, b); atomicAdd(p + 2, c); atomicAdd(p + 3, d);
#endif
}
__device__ __forceinline__ void red_add_v2(float* p, float a, float b) {
#if defined(__CUDA_ARCH__) && __CUDA_ARCH__ >= 900
    asm volatile("red.global.add.v2.f32 [%0], {%1, %2};"
                 :: "l"(p), "f"(a), "f"(b) : "memory");
#else
    atomicAdd(p + 0, a); atomicAdd(p + 1, b);
#endif
}

// ---------------- main sparse-conv (BN+ReLU-fused gather - GEMM - scatter-add) --
// Tile: 128 compacted rows x COLS cols. Full W[k] stays in smem (reused across
// consecutive same-k tiles); activations chunked over K by KC to cut smem.
// Blocks own contiguous (cc-outer, tile-inner) ranges for W reuse.
// (R10-winning scalar mainloop.)
template <int CIN, int KC, int COLS, bool BN, int MAXB>
__global__ void __launch_bounds__(16 * (COLS / 4), MAXB)
conv_scatter(const float* __restrict__ xA, const float* __restrict__ xB, int wA,
             const float* __restrict__ ssA, const float* __restrict__ ssB,
             const float* __restrict__ W, float* __restrict__ out,
             int COUT, int nCC,
             const int2* __restrict__ pairs, const int* __restrict__ cur) {
    constexpr int T   = 16 * (COLS / 4);   // threads
    constexpr int XST = KC + 4;            // xs row stride (float4-aligned)
    constexpr int NCH = CIN / KC;          // K chunks
    constexpr int TPR = T / 128;           // threads per row in gather
    constexpr int L   = KC / TPR;          // cols per gather thread per chunk
    constexpr int F4  = L / 4;

    extern __shared__ float sm[];
    float* xs = sm;                 // 128 * XST
    float* Ws = sm + 128 * XST;     // CIN * COLS (full K)
    __shared__ float sss[CIN];
    __shared__ float sst[CIN];
    __shared__ int sj[128];
    __shared__ int scnt[27];
    __shared__ int sbase[28];

    const int tid = threadIdx.x;
    if (BN) {
        for (int c = tid; c < CIN; c += T) {
            const float* tab = (c < wA) ? ssA : ssB;
            int cc = (c < wA) ? c : c - wA;
            sss[c] = tab[cc];
            sst[c] = tab[128 + cc];
        }
    }
    if (tid < 27) scnt[tid] = cur[tid];
    __syncthreads();
    if (tid == 0) {
        int s = 0;
        for (int k = 0; k < 27; k++) { sbase[k] = s; s += (scnt[k] + 127) >> 7; }
        sbase[27] = s;
    }
    __syncthreads();
    const int nTiles = sbase[27];
    const long totalT = (long)nTiles * nCC;
    const int tx = tid % (COLS / 4);
    const int ty = tid / (COLS / 4);
    const int gr = tid / TPR;       // gather row
    const int gpart = tid - gr * TPR;

    const long tBeg = (long)blockIdx.x * totalT / gridDim.x;
    const long tEnd = ((long)blockIdx.x + 1) * totalT / gridDim.x;

    int kPrev = -1, ccPrev = -1;

    for (long t = tBeg; t < tEnd; t++) {
        const int cc = (int)(t / nTiles);       // cc outer -> same-k runs adjacent
        const int tileId = (int)(t - (long)cc * nTiles);
        int k = 0;
        while (sbase[k + 1] <= tileId) k++;
        const int rowBase = (tileId - sbase[k]) * 128;
        const int valid = min(scnt[k] - rowBase, 128);
        const int2* pk = &pairs[(size_t)k * MAXPERK + rowBase];
        const int colBase = cc * COLS;

        __syncthreads();  // previous tile's smem reads complete

        // load full W[k] column chunk into smem (skip if unchanged)
        if (k != kPrev || cc != ccPrev) {
            kPrev = k; ccPrev = cc;
            const float* Wk = W + ((size_t)k * CIN) * COUT + colBase;
            #pragma unroll
            for (int idx = tid; idx < CIN * (COLS / 4); idx += T) {
                int ci = idx / (COLS / 4);
                int c4 = idx - ci * (COLS / 4);
                *(float4*)&Ws[ci * COLS + c4 * 4] =
                    *(const float4*)&Wk[(size_t)ci * COUT + c4 * 4];
            }
        }

        // per-tile row pair (held in regs across chunks)
        int2 prw = (gr < valid) ? pk[gr] : make_int2(-1, -1);
        if (gpart == 0) sj[gr] = prw.x;

        float acc[8][4];
        #pragma unroll
        for (int i = 0; i < 8; i++)
            acc[i][0] = acc[i][1] = acc[i][2] = acc[i][3] = 0.f;

        #pragma unroll
        for (int kc = 0; kc < NCH; kc++) {
            if (kc > 0) __syncthreads();   // prev chunk's xs reads complete

            // gather chunk kc, BN+ReLU applied on the fly
            {
                const int c0 = kc * KC + gpart * L;   // global column
                float4* dst = (float4*)&xs[gr * XST + gpart * L];
                if (prw.x >= 0) {
                    const float4* src = (c0 < wA)
                        ? (const float4*)(xA + (size_t)prw.y * wA + c0)
                        : (const float4*)(xB + (size_t)prw.y * (CIN - wA) + (c0 - wA));
                    #pragma unroll
                    for (int v = 0; v < F4; v++) {
                        float4 q = src[v];
                        if (BN) {
                            const int c = c0 + 4 * v;
                            q.x = fmaxf(fmaf(q.x, sss[c + 0], sst[c + 0]), 0.f);
                            q.y = fmaxf(fmaf(q.y, sss[c + 1], sst[c + 1]), 0.f);
                            q.z = fmaxf(fmaf(q.z, sss[c + 2], sst[c + 2]), 0.f);
                            q.w = fmaxf(fmaf(q.w, sss[c + 3], sst[c + 3]), 0.f);
                        }
                        dst[v] = q;
                    }
                } else {
                    #pragma unroll
                    for (int v = 0; v < F4; v++)
                        dst[v] = make_float4(0.f, 0.f, 0.f, 0.f);
                }
            }
            __syncthreads();

            // FFMA over this K chunk (all LDS are .128)
            #pragma unroll 2
            for (int ci = 0; ci < KC; ci += 4) {
                const int wrow = kc * KC + ci;
                const float4 w0 = *(const float4*)&Ws[(wrow + 0) * COLS + tx * 4];
                const float4 w1 = *(const float4*)&Ws[(wrow + 1) * COLS + tx * 4];
                const float4 w2 = *(const float4*)&Ws[(wrow + 2) * COLS + tx * 4];
                const float4 w3 = *(const float4*)&Ws[(wrow + 3) * COLS + tx * 4];
                #pragma unroll
                for (int i = 0; i < 8; i++) {
                    const float4 a = *(const float4*)&xs[(ty * 8 + i) * XST + ci];
                    acc[i][0] += a.x * w0.x; acc[i][1] += a.x * w0.y;
                    acc[i][2] += a.x * w0.z; acc[i][3] += a.x * w0.w;
                    acc[i][0] += a.y * w1.x; acc[i][1] += a.y * w1.y;
                    acc[i][2] += a.y * w1.z; acc[i][3] += a.y * w1.w;
                    acc[i][0] += a.z * w2.x; acc[i][1] += a.z * w2.y;
                    acc[i][2] += a.z * w2.z; acc[i][3] += a.z * w2.w;
                    acc[i][0] += a.w * w3.x; acc[i][1] += a.w * w3.y;
                    acc[i][2] += a.w * w3.z; acc[i][3] += a.w * w3.w;
                }
            }
        }

        // scatter-add (cross-k collisions need atomics) — 128-bit reds
        #pragma unroll
        for (int i = 0; i < 8; i++) {
            const int r = ty * 8 + i;
            if (r < valid) {
                float* op = out + (size_t)sj[r] * COUT + colBase + tx * 4;
                red_add_v4(op, acc[i][0], acc[i][1], acc[i][2], acc[i][3]);
            }
        }
    }
}

// ---------------- fused: BN stats+finalize (512 blocks) | zero next buffer
// (256 blocks) | fill next map (rest). Roles run concurrently in one launch.
__global__ void statsfused_kernel(const float* __restrict__ t, int n, int C,
                                  const float* __restrict__ g, const float* __restrict__ b,
                                  float* __restrict__ stats, float* __restrict__ ss,
                                  int* __restrict__ cnt,
                                  float* __restrict__ zp, long zn,
                                  const int* __restrict__ map, int Nout,
                                  int2* __restrict__ pairs, int* __restrict__ cur) {
    __shared__ float4 r1[256], r2[256];
    __shared__ int last;
    const int tid = threadIdx.x;
    const int bid = blockIdx.x;

    if (bid < 512) {
        // ---- stats role (vectorized float4) ----
        const int c4n = C / 4;          // 8 / 16 / 32
        const int c4 = tid % c4n;
        const int gi = tid / c4n;
        const int G = 256 / c4n;
        const float4* t4 = (const float4*)t;
        float4 a = make_float4(0.f, 0.f, 0.f, 0.f);
        float4 q = make_float4(0.f, 0.f, 0.f, 0.f);
        for (long row = (long)bid * G + gi; row < n; row += 512L * G) {
            float4 v = t4[row * c4n + c4];
            a.x += v.x; a.y += v.y; a.z += v.z; a.w += v.w;
            q.x += v.x * v.x; q.y += v.y * v.y; q.z += v.z * v.z; q.w += v.w * v.w;
        }
        r1[tid] = a; r2[tid] = q;
        __syncthreads();
        for (int off = 128; off >= c4n; off >>= 1) {
            if (tid < off) {
                float4 x1 = r1[tid + off], x2 = r2[tid + off];
                float4 y1 = r1[tid], y2 = r2[tid];
                y1.x += x1.x; y1.y += x1.y; y1.z += x1.z; y1.w += x1.w;
                y2.x += x2.x; y2.y += x2.y; y2.z += x2.z; y2.w += x2.w;
                r1[tid] = y1; r2[tid] = y2;
            }
            __syncthreads();
        }
        if (tid < c4n) {
            float4 a4 = r1[tid], q4 = r2[tid];
            atomicAdd(&stats[4 * tid + 0], a4.x);
            atomicAdd(&stats[4 * tid + 1], a4.y);
            atomicAdd(&stats[4 * tid + 2], a4.z);
            atomicAdd(&stats[4 * tid + 3], a4.w);
            atomicAdd(&stats[128 + 4 * tid + 0], q4.x);
            atomicAdd(&stats[128 + 4 * tid + 1], q4.y);
            atomicAdd(&stats[128 + 4 * tid + 2], q4.z);
            atomicAdd(&stats[128 + 4 * tid + 3], q4.w);
        }
        __threadfence();
        if (tid == 0) last = (atomicAdd(cnt, 1) == 511);
        __syncthreads();
        if (last && tid < C) {
            volatile float* vs = stats;
            float inv = 1.f / (float)n;
            float mu = vs[tid] * inv;
            float var = vs[128 + tid] * inv - mu * mu;
            float s = g[tid] * rsqrtf(var + 1e-5f);
            ss[tid] = s;
            ss[128 + tid] = b[tid] - mu * s;
        }
    } else if (bid < 768) {
        // ---- zero role ----
        const int bz = bid - 512;
        long n4 = zn >> 2;
        float4* p4 = (float4*)zp;
        for (long i = (long)bz * 256 + tid; i < n4; i += 256L * 256)
            p4[i] = make_float4(0.f, 0.f, 0.f, 0.f);
        if (bz == 0 && tid < (zn & 3)) zp[n4 * 4 + tid] = 0.f;
    } else {
        // ---- fill role ----
        fill_body((bid - 768) * 256 + tid, map, Nout, pairs, cur);
    }
}

// ---------------- final 96 -> 2 conv (thread per compacted pair, BN in gather) --
__global__ void conv_final_kernel(const float* __restrict__ xA,   // tmp1t [*,64]
                                  const float* __restrict__ xB,   // tmp0  [*,32]
                                  const float* __restrict__ ssA,
                                  const float* __restrict__ ssB,
                                  const float* __restrict__ W, float* __restrict__ out,
                                  const int2* __restrict__ pairs,
                                  const int* __restrict__ cur) {
    __shared__ float Ws[27 * 96 * 2];
    __shared__ float sss[96], sst[96];
    __shared__ int scnt[27];
    __shared__ int sbase[28];
    int tid = threadIdx.x;
    for (int i = tid; i < 27 * 192; i += 256) Ws[i] = W[i];
    for (int c = tid; c < 96; c += 256) {
        const float* tab = (c < 64) ? ssA : ssB;
        int cc = (c < 64) ? c : c - 64;
        sss[c] = tab[cc];
        sst[c] = tab[128 + cc];
    }
    if (tid < 27) scnt[tid] = cur[tid];
    __syncthreads();
    if (tid == 0) {
        int s = 0;
        for (int k = 0; k < 27; k++) { sbase[k] = s; s += (scnt[k] + 255) >> 8; }
        sbase[27] = s;
    }
    __syncthreads();
    int total = sbase[27];
    for (int t = blockIdx.x; t < total; t += gridDim.x) {
        int k = 0;
        while (sbase[k + 1] <= t) k++;
        int pi = (t - sbase[k]) * 256 + tid;
        if (pi < scnt[k]) {
            int2 p = pairs[(size_t)k * MAXPERK + pi];
            const float* wk = &Ws[k * 192];
            float a0 = 0.f, a1 = 0.f;
            const float4* rA = (const float4*)(xA + (size_t)p.y * 64);
            #pragma unroll
            for (int v = 0; v < 16; v++) {
                float4 q = rA[v];
                int c = 4 * v;
                q.x = fmaxf(fmaf(q.x, sss[c + 0], sst[c + 0]), 0.f);
                q.y = fmaxf(fmaf(q.y, sss[c + 1], sst[c + 1]), 0.f);
                q.z = fmaxf(fmaf(q.z, sss[c + 2], sst[c + 2]), 0.f);
                q.w = fmaxf(fmaf(q.w, sss[c + 3], sst[c + 3]), 0.f);
                a0 += q.x * wk[(c + 0) * 2 + 0]; a1 += q.x * wk[(c + 0) * 2 + 1];
                a0 += q.y * wk[(c + 1) * 2 + 0]; a1 += q.y * wk[(c + 1) * 2 + 1];
                a0 += q.z * wk[(c + 2) * 2 + 0]; a1 += q.z * wk[(c + 2) * 2 + 1];
                a0 += q.w * wk[(c + 3) * 2 + 0]; a1 += q.w * wk[(c + 3) * 2 + 1];
            }
            const float4* rB = (const float4*)(xB + (size_t)p.y * 32);
            #pragma unroll
            for (int v = 0; v < 8; v++) {
                float4 q = rB[v];
                int c = 64 + 4 * v;
                q.x = fmaxf(fmaf(q.x, sss[c + 0], sst[c + 0]), 0.f);
                q.y = fmaxf(fmaf(q.y, sss[c + 1], sst[c + 1]), 0.f);
                q.z = fmaxf(fmaf(q.z, sss[c + 2], sst[c + 2]), 0.f);
                q.w = fmaxf(fmaf(q.w, sss[c + 3], sst[c + 3]), 0.f);
                a0 += q.x * wk[(c + 0) * 2 + 0]; a1 += q.x * wk[(c + 0) * 2 + 1];
                a0 += q.y * wk[(c + 1) * 2 + 0]; a1 += q.y * wk[(c + 1) * 2 + 1];
                a0 += q.z * wk[(c + 2) * 2 + 0]; a1 += q.z * wk[(c + 2) * 2 + 1];
                a0 += q.w * wk[(c + 3) * 2 + 0]; a1 += q.w * wk[(c + 3) * 2 + 1];
            }
            red_add_v2(&out[(size_t)p.x * 2], a0, a1);
        }
    }
}

// ---------------- host orchestration ----------------
extern "C" void kernel_launch(void* const* d_in, const int* in_sizes, int n_in,
                              void* d_out, int out_size) {
    if (n_in < 23) return;
    const float* feats = (const float*)d_in[0];
    const float* W0  = (const float*)d_in[1];
    const float* g0  = (const float*)d_in[2];
    const float* b0  = (const float*)d_in[3];
    const float* W1  = (const float*)d_in[4];
    const float* g1  = (const float*)d_in[5];
    const float* b1  = (const float*)d_in[6];
    const float* W2  = (const float*)d_in[7];
    const float* g2  = (const float*)d_in[8];
    const float* b2  = (const float*)d_in[9];
    const float* W2t = (const float*)d_in[10];
    const float* g2t = (const float*)d_in[11];
    const float* b2t = (const float*)d_in[12];
    const float* W1t = (const float*)d_in[13];
    const float* g1t = (const float*)d_in[14];
    const float* b1t = (const float*)d_in[15];
    const float* W0t = (const float*)d_in[16];
    const int* map0  = (const int*)d_in[17];
    const int* map1  = (const int*)d_in[18];
    const int* map2  = (const int*)d_in[19];
    const int* map2t = (const int*)d_in[20];
    const int* map1t = (const int*)d_in[21];
    const int* map0t = (const int*)d_in[22];

    const int N0 = in_sizes[0] / 16;
    const int N1 = in_sizes[18] / 27;
    const int N2 = in_sizes[19] / 27;

    float *t0, *t1, *t2, *t2t, *t1t;
    int2 *pr; int *cu; float *st, *ss; int *cn;
    cudaGetSymbolAddress((void**)&t0,  d_tmp0);
    cudaGetSymbolAddress((void**)&t1,  d_tmp1);
    cudaGetSymbolAddress((void**)&t2,  d_tmp2);
    cudaGetSymbolAddress((void**)&t2t, d_tmp2t);
    cudaGetSymbolAddress((void**)&t1t, d_tmp1t);
    cudaGetSymbolAddress((void**)&pr,  d_pairs2);
    cudaGetSymbolAddress((void**)&cu,  d_cur6);
    cudaGetSymbolAddress((void**)&st,  d_stats6);
    cudaGetSymbolAddress((void**)&ss,  d_ss6);
    cudaGetSymbolAddress((void**)&cn,  d_cnt6);
    const size_t PK = (size_t)27 * MAXPERK;
    // pairs ping-pong: layer l uses buffer l%2 (fill for l+1 only starts after
    // conv l — the previous user of that buffer — has completed, in-stream)
    int2* P[6]; int* C6[6]; float* ST[6]; float* SS[6];
    for (int l = 0; l < 6; l++) {
        P[l] = pr + (l & 1) * PK; C6[l] = cu + l * 32;
        ST[l] = st + l * 256; SS[l] = ss + l * 256;
    }

    // smem: 128*(KC+4)*4 (xs) + CIN*COLS*4 (full Ws)
    const int sm16    = (128 * 20 + 16  * 32) * 4;   // 12288
    const int sm32    = (128 * 36 + 32  * 64) * 4;   // 26624
    const int sm64    = (128 * 68 + 64  * 64) * 4;   // 51200  (R10 config)
    const int sm128_4 = (128 * 36 + 128 * 64) * 4;   // 51200  (KC=32, 4 blocks/SM)
    cudaFuncSetAttribute(conv_scatter<64, 64, 64, true, 3>,
                         cudaFuncAttributeMaxDynamicSharedMemorySize, sm64);
    cudaFuncSetAttribute(conv_scatter<128, 32, 64, true, 4>,
                         cudaFuncAttributeMaxDynamicSharedMemorySize, sm128_4);

    const int GC  = 444;   // 148 SMs x 3 resident blocks
    const int GC4 = 592;   // 148 SMs x 4 resident blocks (CIN=128 occupancy experiment)

    auto cdiv = [](long a, long b) { return (int)((a + b - 1) / b); };
    const int FB0 = cdiv(27L * N0, 256);
    const int FB1 = cdiv(27L * N1, 256);
    const int FB2 = cdiv(27L * N2, 256);

    // global init
    prep_kernel<<<1, 256>>>();
    zero_ptr_kernel<<<512, 256>>>(t0, (long)N0 * 32);

    // ---- Layer 0: feats[N0,16] -> tmp0 (raw), BN fused downstream
    fill_kernel<<<FB0, 256>>>(map0, N0, P[0], C6[0]);
    conv_scatter<16, 16, 32, false, 6><<<888, 128, sm16>>>(
        feats, (const float*)nullptr, 16, nullptr, nullptr, W0, t0, 32, 1, P[0], C6[0]);
    // stats0 | zero t1 | fill map1
    statsfused_kernel<<<768 + FB1, 256>>>(t0, N0, 32, g0, b0, ST[0], SS[0], &cn[0],
                                          t1, (long)N1 * 64, map1, N1, P[1], C6[1]);

    // ---- Layer 1: bn(tmp0) -> tmp1
    conv_scatter<32, 32, 64, true, 3><<<GC, 256, sm32>>>(
        t0, (const float*)nullptr, 32, SS[0], nullptr, W1, t1, 64, 1, P[1], C6[1]);
    statsfused_kernel<<<768 + FB2, 256>>>(t1, N1, 64, g1, b1, ST[1], SS[1], &cn[1],
                                          t2, (long)N2 * 128, map2, N2, P[2], C6[2]);

    // ---- Layer 2: bn(tmp1) -> tmp2
    conv_scatter<64, 64, 64, true, 3><<<GC, 256, sm64>>>(
        t1, (const float*)nullptr, 64, SS[1], nullptr, W2, t2, 128, 2, P[2], C6[2]);
    statsfused_kernel<<<768 + FB1, 256>>>(t2, N2, 128, g2, b2, ST[2], SS[2], &cn[2],
                                          t2t, (long)N1 * 64, map2t, N1, P[3], C6[3]);

    // ---- Layer 2t: bn(tmp2) -> tmp2t  (KC=32, 4 blocks/SM)
    conv_scatter<128, 32, 64, true, 4><<<GC4, 256, sm128_4>>>(
        t2, (const float*)nullptr, 128, SS[2], nullptr, W2t, t2t, 64, 1, P[3], C6[3]);
    statsfused_kernel<<<768 + FB0, 256>>>(t2t, N1, 64, g2t, b2t, ST[3], SS[3], &cn[3],
                                          t1t, (long)N0 * 64, map1t, N0, P[4], C6[4]);

    // ---- Layer 1t: [bn(tmp2t) | bn(tmp1)] (virtual concat, CIN=128) -> tmp1t
    conv_scatter<128, 32, 64, true, 4><<<GC4, 256, sm128_4>>>(
        t2t, t1, 64, SS[3], SS[1], W1t, t1t, 64, 1, P[4], C6[4]);
    statsfused_kernel<<<768 + FB0, 256>>>(t1t, N0, 64, g1t, b1t, ST[4], SS[4], &cn[4],
                                          (float*)d_out, (long)out_size,
                                          map0t, N0, P[5], C6[5]);

    // ---- Layer 0t: [bn(tmp1t) | bn(tmp0)] (virtual concat, CIN=96) -> out[N0,2]
    conv_final_kernel<<<2048, 256>>>(t1t, t0, SS[4], SS[0], W0t,
                                     (float*)d_out, P[5], C6[5]);
}